// round 1
// baseline (speedup 1.0000x reference)
#include <cuda_runtime.h>

#define D_MODEL 1024
#define NHEADS  16
#define HD      64
#define BATCH   2
#define TSEQ    2048
#define M_TOT   (BATCH * TSEQ)   // 4096

// Scratch (allocation-free rule: __device__ globals). Layout:
// g_Q/g_K/g_V: [B*H][T][HD]   g_A: [B*T][D]
__device__ float g_Q[BATCH * NHEADS * TSEQ * HD];
__device__ float g_K[BATCH * NHEADS * TSEQ * HD];
__device__ float g_V[BATCH * NHEADS * TSEQ * HD];
__device__ float g_A[BATCH * TSEQ * D_MODEL];

// ---------------------------------------------------------------------------
// GEMM core: Y[m][n] = sum_k X[m][k] * W[n][k] + bias[n]
// BM=BN=64, BK=16, 256 threads, 4x4 microtile per thread.
// ---------------------------------------------------------------------------
struct GemmAcc {
    float acc[4][4];
};

__device__ __forceinline__ void gemm_body(
    const float* __restrict__ X, const float* __restrict__ W,
    int m0, int n0, GemmAcc& g,
    float (*As)[68], float (*Ws)[68])
{
    int tid = threadIdx.x;
    int tr = tid >> 4;          // 0..15
    int tc = tid & 15;          // 0..15
    int lr = tid >> 2;          // 0..63 (load row)
    int lc = (tid & 3) << 2;    // 0,4,8,12 (load k-offset)

    const float* aptr = X + (size_t)(m0 + lr) * D_MODEL + lc;
    const float* wptr = W + (size_t)(n0 + lr) * D_MODEL + lc;

    for (int k0 = 0; k0 < D_MODEL; k0 += 16) {
        float4 av = *(const float4*)(aptr + k0);
        float4 wv = *(const float4*)(wptr + k0);
        __syncthreads();
        As[lc + 0][lr] = av.x; As[lc + 1][lr] = av.y;
        As[lc + 2][lr] = av.z; As[lc + 3][lr] = av.w;
        Ws[lc + 0][lr] = wv.x; Ws[lc + 1][lr] = wv.y;
        Ws[lc + 2][lr] = wv.z; Ws[lc + 3][lr] = wv.w;
        __syncthreads();
        #pragma unroll
        for (int kk = 0; kk < 16; kk++) {
            float4 a4 = *(const float4*)&As[kk][tr << 2];
            float4 b4 = *(const float4*)&Ws[kk][tc << 2];
            float ar[4] = {a4.x, a4.y, a4.z, a4.w};
            float br[4] = {b4.x, b4.y, b4.z, b4.w};
            #pragma unroll
            for (int i = 0; i < 4; i++)
                #pragma unroll
                for (int j = 0; j < 4; j++)
                    g.acc[i][j] += ar[i] * br[j];
        }
    }
}

// QKV projection: grid (N/64=16, M/64=64, 3). Writes head-major layout.
__global__ __launch_bounds__(256)
void qkv_gemm_kernel(const float* __restrict__ X,
                     const float* __restrict__ Wq, const float* __restrict__ bq,
                     const float* __restrict__ Wk, const float* __restrict__ bk,
                     const float* __restrict__ Wv, const float* __restrict__ bv)
{
    __shared__ __align__(16) float As[16][68];
    __shared__ __align__(16) float Ws[16][68];

    const float* W; const float* bias; float* dst;
    if (blockIdx.z == 0)      { W = Wq; bias = bq; dst = g_Q; }
    else if (blockIdx.z == 1) { W = Wk; bias = bk; dst = g_K; }
    else                      { W = Wv; bias = bv; dst = g_V; }

    int m0 = blockIdx.y * 64, n0 = blockIdx.x * 64;
    GemmAcc g;
    #pragma unroll
    for (int i = 0; i < 4; i++)
        #pragma unroll
        for (int j = 0; j < 4; j++) g.acc[i][j] = 0.f;

    gemm_body(X, W, m0, n0, g, As, Ws);

    int tr = threadIdx.x >> 4, tc = threadIdx.x & 15;
    #pragma unroll
    for (int i = 0; i < 4; i++) {
        int m = m0 + (tr << 2) + i;
        int b = m / TSEQ, t = m - b * TSEQ;
        #pragma unroll
        for (int j = 0; j < 4; j++) {
            int n = n0 + (tc << 2) + j;
            float v = g.acc[i][j] + bias[n];
            int h = n >> 6, d = n & 63;
            dst[(((size_t)b * NHEADS + h) * TSEQ + t) * HD + d] = v;
        }
    }
}

// Output projection: reads g_A, writes plain [B*T][D] to Y.
__global__ __launch_bounds__(256)
void out_gemm_kernel(const float* __restrict__ Wo, const float* __restrict__ bo,
                     float* __restrict__ Y)
{
    __shared__ __align__(16) float As[16][68];
    __shared__ __align__(16) float Ws[16][68];

    int m0 = blockIdx.y * 64, n0 = blockIdx.x * 64;
    GemmAcc g;
    #pragma unroll
    for (int i = 0; i < 4; i++)
        #pragma unroll
        for (int j = 0; j < 4; j++) g.acc[i][j] = 0.f;

    gemm_body(g_A, Wo, m0, n0, g, As, Ws);

    int tr = threadIdx.x >> 4, tc = threadIdx.x & 15;
    #pragma unroll
    for (int i = 0; i < 4; i++) {
        int m = m0 + (tr << 2) + i;
        #pragma unroll
        for (int j = 0; j < 4; j++) {
            int n = n0 + (tc << 2) + j;
            Y[(size_t)m * D_MODEL + n] = g.acc[i][j] + bo[n];
        }
    }
}

// ---------------------------------------------------------------------------
// Attention. grid (T/64=32, B*H=32), 64 threads. Thread t owns query row
// qi = qt*64 + t. Decay bias -(i-j) kills everything beyond delta ~100, so we
// only process key tiles jt in [qt-2, qt] (skipped tiles: delta >= 129 =>
// weight <= e^(6-129) == 0.0f exactly in fp32, identical to the reference).
// ---------------------------------------------------------------------------
__global__ __launch_bounds__(64)
void attn_kernel()
{
    __shared__ __align__(16) float Qt[64][64];  // Qt[d][t]  (transposed)
    __shared__ __align__(16) float Kt[64][64];  // Kt[d][j]  (transposed)
    __shared__ __align__(16) float Vs[64][64];  // Vs[j][d]

    int qt = blockIdx.x;
    int bh = blockIdx.y;
    int t  = threadIdx.x;

    const float* Qb = g_Q + (size_t)bh * TSEQ * HD;
    const float* Kb = g_K + (size_t)bh * TSEQ * HD;
    const float* Vb = g_V + (size_t)bh * TSEQ * HD;

    // Load Q tile (transposed into smem)
    #pragma unroll
    for (int it = 0; it < 16; it++) {
        int f = (it << 6) + t;
        int r = f >> 4, c = (f & 15) << 2;
        float4 v = *(const float4*)&Qb[((size_t)qt * 64 + r) * HD + c];
        Qt[c + 0][r] = v.x; Qt[c + 1][r] = v.y;
        Qt[c + 2][r] = v.z; Qt[c + 3][r] = v.w;
    }

    float o[64];
    #pragma unroll
    for (int d = 0; d < 64; d++) o[d] = 0.f;
    float mrun = -1e30f, l = 0.f;
    int qi = qt * 64 + t;

    int jt0 = (qt >= 2) ? (qt - 2) : 0;
    for (int jt = jt0; jt <= qt; jt++) {
        __syncthreads();
        #pragma unroll
        for (int it = 0; it < 16; it++) {
            int f = (it << 6) + t;
            int r = f >> 4, c = (f & 15) << 2;
            float4 kv = *(const float4*)&Kb[((size_t)jt * 64 + r) * HD + c];
            Kt[c + 0][r] = kv.x; Kt[c + 1][r] = kv.y;
            Kt[c + 2][r] = kv.z; Kt[c + 3][r] = kv.w;
            float4 vv = *(const float4*)&Vb[((size_t)jt * 64 + r) * HD + c];
            *(float4*)&Vs[r][c] = vv;
        }
        __syncthreads();

        // S row: s[j] = q . k_j   (Qt read conflict-free, Kt broadcast)
        float s[64];
        #pragma unroll
        for (int j = 0; j < 64; j++) s[j] = 0.f;
        #pragma unroll 4
        for (int d = 0; d < 64; d++) {
            float qd = Qt[d][t];
            #pragma unroll
            for (int j4 = 0; j4 < 16; j4++) {
                float4 k4 = *(const float4*)&Kt[d][j4 << 2];
                s[4 * j4 + 0] += qd * k4.x;
                s[4 * j4 + 1] += qd * k4.y;
                s[4 * j4 + 2] += qd * k4.z;
                s[4 * j4 + 3] += qd * k4.w;
            }
        }

        // mask + decay bias + tile max
        float tmax = -1e30f;
        int base = jt * 64;
        #pragma unroll
        for (int j = 0; j < 64; j++) {
            int kj = base + j;
            float sc = (kj <= qi) ? (s[j] * 0.125f - (float)(qi - kj)) : -1e30f;
            s[j] = sc;
            tmax = fmaxf(tmax, sc);
        }
        float mnew = fmaxf(mrun, tmax);
        float corr = __expf(mrun - mnew);
        l *= corr;
        #pragma unroll
        for (int d = 0; d < 64; d++) o[d] *= corr;

        #pragma unroll
        for (int j = 0; j < 64; j++) {
            float p = __expf(s[j] - mnew);
            s[j] = p;
            l += p;
        }
        mrun = mnew;

        // O += P @ V  (Vs reads are broadcast)
        #pragma unroll
        for (int j = 0; j < 64; j++) {
            float pj = s[j];
            #pragma unroll
            for (int d4 = 0; d4 < 16; d4++) {
                float4 v4 = *(const float4*)&Vs[j][d4 << 2];
                o[4 * d4 + 0] += pj * v4.x;
                o[4 * d4 + 1] += pj * v4.y;
                o[4 * d4 + 2] += pj * v4.z;
                o[4 * d4 + 3] += pj * v4.w;
            }
        }
    }

    float inv = 1.0f / l;
    int b = bh >> 4, h = bh & 15;
    float* dst = g_A + ((size_t)b * TSEQ + qi) * D_MODEL + h * HD;
    #pragma unroll
    for (int d4 = 0; d4 < 16; d4++) {
        float4 v;
        v.x = o[4 * d4 + 0] * inv;
        v.y = o[4 * d4 + 1] * inv;
        v.z = o[4 * d4 + 2] * inv;
        v.w = o[4 * d4 + 3] * inv;
        *(float4*)&dst[d4 << 2] = v;
    }
}

// ---------------------------------------------------------------------------
extern "C" void kernel_launch(void* const* d_in, const int* in_sizes, int n_in,
                              void* d_out, int out_size)
{
    const float* x  = (const float*)d_in[0];
    const float* Wq = (const float*)d_in[1];
    const float* bq = (const float*)d_in[2];
    const float* Wk = (const float*)d_in[3];
    const float* bk = (const float*)d_in[4];
    const float* Wv = (const float*)d_in[5];
    const float* bv = (const float*)d_in[6];
    const float* Wo = (const float*)d_in[7];
    const float* bo = (const float*)d_in[8];
    float* out = (float*)d_out;

    dim3 ggrid(D_MODEL / 64, M_TOT / 64, 3);
    qkv_gemm_kernel<<<ggrid, 256>>>(x, Wq, bq, Wk, bk, Wv, bv);

    dim3 agrid(TSEQ / 64, BATCH * NHEADS);
    attn_kernel<<<agrid, 64>>>();

    dim3 ogrid(D_MODEL / 64, M_TOT / 64);
    out_gemm_kernel<<<ogrid, 256>>>(Wo, bo, out);
}

// round 3
// speedup vs baseline: 1.0745x; 1.0745x over previous
#include <cuda_runtime.h>

#define D_MODEL 1024
#define NHEADS  16
#define HD      64
#define BATCH   2
#define TSEQ    2048
#define M_TOT   (BATCH * TSEQ)   // 4096

#define BM 128
#define BN 128
#define BK 8

// Scratch (allocation-free rule: __device__ globals).
// g_Q/g_K/g_V: [B*H][T][HD]   g_A: [B*T][D]
__device__ float g_Q[BATCH * NHEADS * TSEQ * HD];
__device__ float g_K[BATCH * NHEADS * TSEQ * HD];
__device__ float g_V[BATCH * NHEADS * TSEQ * HD];
__device__ float g_A[BATCH * TSEQ * D_MODEL];

// ---------------------------------------------------------------------------
// SGEMM core: acc[i][j] = sum_k X[m0+ty*8+i][k] * W[n0+tx*8+j][k]
// 128x128x8 block tile, 256 threads, 8x8 microtile, double-buffered smem,
// register prefetch of the next global stage. One __syncthreads per K-step.
// ---------------------------------------------------------------------------
__device__ __forceinline__ void sgemm_core(
    const float* __restrict__ X, const float* __restrict__ W,
    int m0, int n0,
    float (*As)[BK][BM], float (*Bs)[BK][BN],
    float acc[8][8])
{
    const int tid  = threadIdx.x;
    const int lrow = tid >> 1;          // 0..127
    const int lcol = (tid & 1) << 2;    // 0 or 4
    const int tx   = tid & 15;          // 0..15  (n groups)
    const int ty   = tid >> 4;          // 0..15  (m groups)

    const float* xp = X + (size_t)(m0 + lrow) * D_MODEL + lcol;
    const float* wp = W + (size_t)(n0 + lrow) * D_MODEL + lcol;

    // prologue: stage 0
    {
        float4 xa = *(const float4*)xp;
        float4 wa = *(const float4*)wp;
        As[0][lcol + 0][lrow] = xa.x; As[0][lcol + 1][lrow] = xa.y;
        As[0][lcol + 2][lrow] = xa.z; As[0][lcol + 3][lrow] = xa.w;
        Bs[0][lcol + 0][lrow] = wa.x; Bs[0][lcol + 1][lrow] = wa.y;
        Bs[0][lcol + 2][lrow] = wa.z; Bs[0][lcol + 3][lrow] = wa.w;
    }
    __syncthreads();

    int buf = 0;
    for (int k0 = BK; k0 <= D_MODEL; k0 += BK) {
        // prefetch next stage into registers (hidden under compute)
        float4 xn, wn;
        const bool more = (k0 < D_MODEL);
        if (more) {
            xn = *(const float4*)(xp + k0);
            wn = *(const float4*)(wp + k0);
        }

        // compute current stage
        #pragma unroll
        for (int kk = 0; kk < BK; kk++) {
            float4 a0 = *(const float4*)&As[buf][kk][ty << 3];
            float4 a1 = *(const float4*)&As[buf][kk][(ty << 3) + 4];
            float4 b0 = *(const float4*)&Bs[buf][kk][tx << 3];
            float4 b1 = *(const float4*)&Bs[buf][kk][(tx << 3) + 4];
            float a[8] = {a0.x, a0.y, a0.z, a0.w, a1.x, a1.y, a1.z, a1.w};
            float b[8] = {b0.x, b0.y, b0.z, b0.w, b1.x, b1.y, b1.z, b1.w};
            #pragma unroll
            for (int i = 0; i < 8; i++)
                #pragma unroll
                for (int j = 0; j < 8; j++)
                    acc[i][j] += a[i] * b[j];
        }

        if (more) {
            const int nb = buf ^ 1;
            As[nb][lcol + 0][lrow] = xn.x; As[nb][lcol + 1][lrow] = xn.y;
            As[nb][lcol + 2][lrow] = xn.z; As[nb][lcol + 3][lrow] = xn.w;
            Bs[nb][lcol + 0][lrow] = wn.x; Bs[nb][lcol + 1][lrow] = wn.y;
            Bs[nb][lcol + 2][lrow] = wn.z; Bs[nb][lcol + 3][lrow] = wn.w;
            __syncthreads();
            buf = nb;
        }
    }
}

// QKV projection: grid (N/128=8, M/128=32, 3). Writes head-major layout.
__global__ __launch_bounds__(256)
void qkv_gemm_kernel(const float* __restrict__ X,
                     const float* __restrict__ Wq, const float* __restrict__ bq,
                     const float* __restrict__ Wk, const float* __restrict__ bk,
                     const float* __restrict__ Wv, const float* __restrict__ bv)
{
    __shared__ __align__(16) float As[2][BK][BM];
    __shared__ __align__(16) float Bs[2][BK][BN];

    const float* W; const float* bias; float* dst;
    if (blockIdx.z == 0)      { W = Wq; bias = bq; dst = g_Q; }
    else if (blockIdx.z == 1) { W = Wk; bias = bk; dst = g_K; }
    else                      { W = Wv; bias = bv; dst = g_V; }

    const int m0 = blockIdx.y * BM, n0 = blockIdx.x * BN;
    float acc[8][8];
    #pragma unroll
    for (int i = 0; i < 8; i++)
        #pragma unroll
        for (int j = 0; j < 8; j++) acc[i][j] = 0.f;

    sgemm_core(X, W, m0, n0, As, Bs, acc);

    const int tx = threadIdx.x & 15, ty = threadIdx.x >> 4;
    const int nb = n0 + (tx << 3);
    float4 bv0 = *(const float4*)&bias[nb];
    float4 bv1 = *(const float4*)&bias[nb + 4];

    #pragma unroll
    for (int i = 0; i < 8; i++) {
        const int m = m0 + (ty << 3) + i;
        const int b = m >> 11;          // /TSEQ
        const int t = m & (TSEQ - 1);
        // 8 consecutive n stay within one head (8 | 64)
        const int h = nb >> 6, d = nb & 63;
        float* drow = dst + (((size_t)b * NHEADS + h) * TSEQ + t) * HD + d;
        float4 v0, v1;
        v0.x = acc[i][0] + bv0.x; v0.y = acc[i][1] + bv0.y;
        v0.z = acc[i][2] + bv0.z; v0.w = acc[i][3] + bv0.w;
        v1.x = acc[i][4] + bv1.x; v1.y = acc[i][5] + bv1.y;
        v1.z = acc[i][6] + bv1.z; v1.w = acc[i][7] + bv1.w;
        *(float4*)drow       = v0;
        *(float4*)(drow + 4) = v1;
    }
}

// Output projection: reads g_A, writes plain [B*T][D] to Y.
__global__ __launch_bounds__(256)
void out_gemm_kernel(const float* __restrict__ Wo, const float* __restrict__ bo,
                     float* __restrict__ Y)
{
    __shared__ __align__(16) float As[2][BK][BM];
    __shared__ __align__(16) float Bs[2][BK][BN];

    const int m0 = blockIdx.y * BM, n0 = blockIdx.x * BN;
    float acc[8][8];
    #pragma unroll
    for (int i = 0; i < 8; i++)
        #pragma unroll
        for (int j = 0; j < 8; j++) acc[i][j] = 0.f;

    sgemm_core(g_A, Wo, m0, n0, As, Bs, acc);

    const int tx = threadIdx.x & 15, ty = threadIdx.x >> 4;
    const int nb = n0 + (tx << 3);
    float4 bv0 = *(const float4*)&bo[nb];
    float4 bv1 = *(const float4*)&bo[nb + 4];

    #pragma unroll
    for (int i = 0; i < 8; i++) {
        const int m = m0 + (ty << 3) + i;
        float* drow = Y + (size_t)m * D_MODEL + nb;
        float4 v0, v1;
        v0.x = acc[i][0] + bv0.x; v0.y = acc[i][1] + bv0.y;
        v0.z = acc[i][2] + bv0.z; v0.w = acc[i][3] + bv0.w;
        v1.x = acc[i][4] + bv1.x; v1.y = acc[i][5] + bv1.y;
        v1.z = acc[i][6] + bv1.z; v1.w = acc[i][7] + bv1.w;
        *(float4*)drow       = v0;
        *(float4*)(drow + 4) = v1;
    }
}

// ---------------------------------------------------------------------------
// Attention. grid (T/64=32, B*H=32), 64 threads. Thread t owns query row
// qi = qt*64 + t. Decay bias -(i-j) kills everything beyond delta ~100, so we
// only process key tiles jt in [qt-2, qt] (skipped tiles: delta >= 129 =>
// weight underflows to exactly 0.0f, identical to the reference softmax).
// ---------------------------------------------------------------------------
__global__ __launch_bounds__(64)
void attn_kernel()
{
    __shared__ __align__(16) float Qt[64][64];  // Qt[d][t]  (transposed)
    __shared__ __align__(16) float Kt[64][64];  // Kt[d][j]  (transposed)
    __shared__ __align__(16) float Vs[64][64];  // Vs[j][d]

    int qt = blockIdx.x;
    int bh = blockIdx.y;
    int t  = threadIdx.x;

    const float* Qb = g_Q + (size_t)bh * TSEQ * HD;
    const float* Kb = g_K + (size_t)bh * TSEQ * HD;
    const float* Vb = g_V + (size_t)bh * TSEQ * HD;

    #pragma unroll
    for (int it = 0; it < 16; it++) {
        int f = (it << 6) + t;
        int r = f >> 4, c = (f & 15) << 2;
        float4 v = *(const float4*)&Qb[((size_t)qt * 64 + r) * HD + c];
        Qt[c + 0][r] = v.x; Qt[c + 1][r] = v.y;
        Qt[c + 2][r] = v.z; Qt[c + 3][r] = v.w;
    }

    float o[64];
    #pragma unroll
    for (int d = 0; d < 64; d++) o[d] = 0.f;
    float mrun = -1e30f, l = 0.f;
    int qi = qt * 64 + t;

    int jt0 = (qt >= 2) ? (qt - 2) : 0;
    for (int jt = jt0; jt <= qt; jt++) {
        __syncthreads();
        #pragma unroll
        for (int it = 0; it < 16; it++) {
            int f = (it << 6) + t;
            int r = f >> 4, c = (f & 15) << 2;
            float4 kv = *(const float4*)&Kb[((size_t)jt * 64 + r) * HD + c];
            Kt[c + 0][r] = kv.x; Kt[c + 1][r] = kv.y;
            Kt[c + 2][r] = kv.z; Kt[c + 3][r] = kv.w;
            float4 vv = *(const float4*)&Vb[((size_t)jt * 64 + r) * HD + c];
            *(float4*)&Vs[r][c] = vv;
        }
        __syncthreads();

        float s[64];
        #pragma unroll
        for (int j = 0; j < 64; j++) s[j] = 0.f;
        #pragma unroll 4
        for (int d = 0; d < 64; d++) {
            float qd = Qt[d][t];
            #pragma unroll
            for (int j4 = 0; j4 < 16; j4++) {
                float4 k4 = *(const float4*)&Kt[d][j4 << 2];
                s[4 * j4 + 0] += qd * k4.x;
                s[4 * j4 + 1] += qd * k4.y;
                s[4 * j4 + 2] += qd * k4.z;
                s[4 * j4 + 3] += qd * k4.w;
            }
        }

        float tmax = -1e30f;
        int base = jt * 64;
        #pragma unroll
        for (int j = 0; j < 64; j++) {
            int kj = base + j;
            float sc = (kj <= qi) ? (s[j] * 0.125f - (float)(qi - kj)) : -1e30f;
            s[j] = sc;
            tmax = fmaxf(tmax, sc);
        }
        float mnew = fmaxf(mrun, tmax);
        float corr = __expf(mrun - mnew);
        l *= corr;
        #pragma unroll
        for (int d = 0; d < 64; d++) o[d] *= corr;

        #pragma unroll
        for (int j = 0; j < 64; j++) {
            float p = __expf(s[j] - mnew);
            s[j] = p;
            l += p;
        }
        mrun = mnew;

        #pragma unroll
        for (int j = 0; j < 64; j++) {
            float pj = s[j];
            #pragma unroll
            for (int d4 = 0; d4 < 16; d4++) {
                float4 v4 = *(const float4*)&Vs[j][d4 << 2];
                o[4 * d4 + 0] += pj * v4.x;
                o[4 * d4 + 1] += pj * v4.y;
                o[4 * d4 + 2] += pj * v4.z;
                o[4 * d4 + 3] += pj * v4.w;
            }
        }
    }

    float inv = 1.0f / l;
    int b = bh >> 4, h = bh & 15;
    float* dst = g_A + ((size_t)b * TSEQ + qi) * D_MODEL + h * HD;
    #pragma unroll
    for (int d4 = 0; d4 < 16; d4++) {
        float4 v;
        v.x = o[4 * d4 + 0] * inv;
        v.y = o[4 * d4 + 1] * inv;
        v.z = o[4 * d4 + 2] * inv;
        v.w = o[4 * d4 + 3] * inv;
        *(float4*)&dst[d4 << 2] = v;
    }
}

// ---------------------------------------------------------------------------
extern "C" void kernel_launch(void* const* d_in, const int* in_sizes, int n_in,
                              void* d_out, int out_size)
{
    const float* x  = (const float*)d_in[0];
    const float* Wq = (const float*)d_in[1];
    const float* bq = (const float*)d_in[2];
    const float* Wk = (const float*)d_in[3];
    const float* bk = (const float*)d_in[4];
    const float* Wv = (const float*)d_in[5];
    const float* bv = (const float*)d_in[6];
    const float* Wo = (const float*)d_in[7];
    const float* bo = (const float*)d_in[8];
    float* out = (float*)d_out;

    dim3 ggrid(D_MODEL / BN, M_TOT / BM, 3);
    qkv_gemm_kernel<<<ggrid, 256>>>(x, Wq, bq, Wk, bk, Wv, bv);

    dim3 agrid(TSEQ / 64, BATCH * NHEADS);
    attn_kernel<<<agrid, 64>>>();

    dim3 ogrid(D_MODEL / BN, M_TOT / BM);
    out_gemm_kernel<<<ogrid, 256>>>(Wo, bo, out);
}

// round 4
// speedup vs baseline: 2.2507x; 2.0947x over previous
#include <cuda_runtime.h>
#include <cuda_bf16.h>

#define D_MODEL 1024
#define NHEADS  16
#define HD      64
#define BATCH   2
#define TSEQ    2048
#define M_TOT   (BATCH * TSEQ)   // 4096

// Scratch (allocation-free rule: __device__ globals).
__device__ float g_Q[BATCH * NHEADS * TSEQ * HD];
__device__ float g_K[BATCH * NHEADS * TSEQ * HD];
__device__ float g_V[BATCH * NHEADS * TSEQ * HD];
__device__ float g_A[BATCH * TSEQ * D_MODEL];

// ---------------------------------------------------------------------------
// bf16-split tensor-core GEMM:  Y[m][n] = sum_k X[m][k] * W[n][k] (+ bias)
// Block 128x128x16, 256 threads (8 warps = 2m x 4n), warp tile 64x32.
// X,W are fp32 in gmem; converted inline to bf16 hi/lo pairs in smem.
// Y = Xhi*Whi + Xhi*Wlo + Xlo*Whi  (lo*lo dropped, rel err ~1e-6).
//
// smem row layout per operand row (m or n): 80 bytes:
//   bytes [0..31]  = 16 bf16 "hi"  (k0..k15)
//   bytes [32..63] = 16 bf16 "lo"
//   bytes [64..79] = pad  (80B stride => conflict-free ldmatrix phases)
// ---------------------------------------------------------------------------
#define ROW_BYTES 80
#define STAGE_BYTES (128 * ROW_BYTES)        // 10240 per operand per stage
#define SMEM_TOTAL  (4 * STAGE_BYTES)        // A0,A1,B0,B1 = 40960 B

__device__ __forceinline__ void ldsm_x4(unsigned& r0, unsigned& r1,
                                        unsigned& r2, unsigned& r3,
                                        unsigned addr)
{
    asm volatile("ldmatrix.sync.aligned.m8n8.x4.shared.b16 {%0,%1,%2,%3}, [%4];"
                 : "=r"(r0), "=r"(r1), "=r"(r2), "=r"(r3) : "r"(addr));
}

__device__ __forceinline__ void mma_bf16(float* d, const unsigned* a,
                                         unsigned b0, unsigned b1)
{
    asm volatile(
        "mma.sync.aligned.m16n8k16.row.col.f32.bf16.bf16.f32 "
        "{%0,%1,%2,%3}, {%4,%5,%6,%7}, {%8,%9}, {%0,%1,%2,%3};"
        : "+f"(d[0]), "+f"(d[1]), "+f"(d[2]), "+f"(d[3])
        : "r"(a[0]), "r"(a[1]), "r"(a[2]), "r"(a[3]), "r"(b0), "r"(b1));
}

// Convert 8 consecutive fp32 (two float4) -> 4 packed bf16x2 hi + 4 lo, STS.
__device__ __forceinline__ void cvt8_store(unsigned addr_hi, float4 a, float4 b)
{
    float f[8] = {a.x, a.y, a.z, a.w, b.x, b.y, b.z, b.w};
    unsigned hi[4], lo[4];
    #pragma unroll
    for (int i = 0; i < 4; i++) {
        float x = f[2 * i], y = f[2 * i + 1];
        __nv_bfloat16 hx = __float2bfloat16_rn(x);
        __nv_bfloat16 hy = __float2bfloat16_rn(y);
        float lx = x - __bfloat162float(hx);
        float ly = y - __bfloat162float(hy);
        __nv_bfloat162 hp; hp.x = hx; hp.y = hy;
        __nv_bfloat162 lp = __floats2bfloat162_rn(lx, ly);
        hi[i] = *(unsigned*)&hp;
        lo[i] = *(unsigned*)&lp;
    }
    asm volatile("st.shared.v4.b32 [%0], {%1,%2,%3,%4};"
                 :: "r"(addr_hi), "r"(hi[0]), "r"(hi[1]), "r"(hi[2]), "r"(hi[3]));
    asm volatile("st.shared.v4.b32 [%0], {%1,%2,%3,%4};"
                 :: "r"(addr_hi + 32), "r"(lo[0]), "r"(lo[1]), "r"(lo[2]), "r"(lo[3]));
}

// Core: fills acc[4][4][4] (mi, n8, dreg) for this thread's warp tile.
__device__ __forceinline__ void mma_core(
    const float* __restrict__ X, const float* __restrict__ W,
    int m0, int n0, char* smem, float acc[4][4][4])
{
    const int tid  = threadIdx.x;
    const int lane = tid & 31;
    const int warp = tid >> 5;
    const int wm0  = (warp >> 2) * 64;   // 0 or 64
    const int wn0  = (warp & 3) * 32;    // 0..96

    const int lrow  = tid >> 1;          // 0..127
    const int lhalf = tid & 1;           // 0/1 -> k offset 0/8

    const float* xp = X + (size_t)(m0 + lrow) * D_MODEL + lhalf * 8;
    const float* wp = W + (size_t)(n0 + lrow) * D_MODEL + lhalf * 8;

    const unsigned sAb = (unsigned)__cvta_generic_to_shared(smem);
    const unsigned sBb = sAb + 2 * STAGE_BYTES;

    // store addresses (hi part; lo = +32)
    const unsigned stA = sAb + lrow * ROW_BYTES + lhalf * 16;
    const unsigned stB = sBb + lrow * ROW_BYTES + lhalf * 16;

    // ldmatrix addresses
    const int arow  = lane & 15;
    const int acoff = (lane >> 4) << 4;                      // 0 or 16 bytes
    const unsigned ldA = sAb + (unsigned)(wm0 + arow) * ROW_BYTES + acoff;
    const int brow  = (lane & 7) + ((lane >> 4) << 3);       // 0..15
    const int bcoff = ((lane >> 3) & 1) << 4;
    const unsigned ldB = sBb + (unsigned)(wn0 + brow) * ROW_BYTES + bcoff;

    // prologue: stage 0
    {
        float4 x0 = *(const float4*)xp;
        float4 x1 = *(const float4*)(xp + 4);
        float4 w0 = *(const float4*)wp;
        float4 w1 = *(const float4*)(wp + 4);
        cvt8_store(stA, x0, x1);
        cvt8_store(stB, w0, w1);
    }
    __syncthreads();

    unsigned buf = 0;
    for (int k0 = 16; k0 <= D_MODEL; k0 += 16) {
        const bool more = (k0 < D_MODEL);
        float4 nx0, nx1, nw0, nw1;
        if (more) {
            nx0 = *(const float4*)(xp + k0);
            nx1 = *(const float4*)(xp + k0 + 4);
            nw0 = *(const float4*)(wp + k0);
            nw1 = *(const float4*)(wp + k0 + 4);
        }

        // ---- compute current stage ----
        const unsigned off = buf * STAGE_BYTES;
        unsigned bh[8], bl[8];
        ldsm_x4(bh[0], bh[1], bh[2], bh[3], ldB + off);                    // n chunks 0,1 hi
        ldsm_x4(bh[4], bh[5], bh[6], bh[7], ldB + off + 16 * ROW_BYTES);   // n chunks 2,3 hi
        ldsm_x4(bl[0], bl[1], bl[2], bl[3], ldB + off + 32);               // lo
        ldsm_x4(bl[4], bl[5], bl[6], bl[7], ldB + off + 16 * ROW_BYTES + 32);

        #pragma unroll
        for (int mi = 0; mi < 4; mi++) {
            unsigned ah[4], al[4];
            const unsigned am = ldA + off + (unsigned)(mi * 16) * ROW_BYTES;
            ldsm_x4(ah[0], ah[1], ah[2], ah[3], am);
            ldsm_x4(al[0], al[1], al[2], al[3], am + 32);
            #pragma unroll
            for (int n8 = 0; n8 < 4; n8++) {
                mma_bf16(acc[mi][n8], ah, bh[2 * n8], bh[2 * n8 + 1]);
                mma_bf16(acc[mi][n8], ah, bl[2 * n8], bl[2 * n8 + 1]);
                mma_bf16(acc[mi][n8], al, bh[2 * n8], bh[2 * n8 + 1]);
            }
        }

        if (more) {
            const unsigned o2 = (buf ^ 1u) * STAGE_BYTES;
            cvt8_store(stA + o2, nx0, nx1);
            cvt8_store(stB + o2, nw0, nw1);
            __syncthreads();
            buf ^= 1u;
        }
    }
}

// QKV projection: grid (8, 32, 3). Writes head-major [B*H][T][HD].
__global__ __launch_bounds__(256)
void qkv_gemm_kernel(const float* __restrict__ X,
                     const float* __restrict__ Wq, const float* __restrict__ bq,
                     const float* __restrict__ Wk, const float* __restrict__ bk,
                     const float* __restrict__ Wv, const float* __restrict__ bv)
{
    __shared__ __align__(16) char smem[SMEM_TOTAL];

    const float* W; const float* bias; float* dst;
    if (blockIdx.z == 0)      { W = Wq; bias = bq; dst = g_Q; }
    else if (blockIdx.z == 1) { W = Wk; bias = bk; dst = g_K; }
    else                      { W = Wv; bias = bv; dst = g_V; }

    const int m0 = blockIdx.y * 128, n0 = blockIdx.x * 128;
    float acc[4][4][4];
    #pragma unroll
    for (int i = 0; i < 4; i++)
        #pragma unroll
        for (int j = 0; j < 4; j++)
            #pragma unroll
            for (int r = 0; r < 4; r++) acc[i][j][r] = 0.f;

    mma_core(X, W, m0, n0, smem, acc);

    const int lane = threadIdx.x & 31, warp = threadIdx.x >> 5;
    const int wm0 = (warp >> 2) * 64, wn0 = (warp & 3) * 32;
    const int g = lane >> 2, t = lane & 3;

    #pragma unroll
    for (int n8 = 0; n8 < 4; n8++) {
        const int n = n0 + wn0 + n8 * 8 + 2 * t;
        const float bx = bias[n], by = bias[n + 1];
        const int h = n >> 6, d = n & 63;
        #pragma unroll
        for (int mi = 0; mi < 4; mi++) {
            #pragma unroll
            for (int half = 0; half < 2; half++) {
                const int m = m0 + wm0 + mi * 16 + g + half * 8;
                const int b = m >> 11, tt = m & (TSEQ - 1);
                float2 v;
                v.x = acc[mi][n8][2 * half + 0] + bx;
                v.y = acc[mi][n8][2 * half + 1] + by;
                *(float2*)&dst[(((size_t)b * NHEADS + h) * TSEQ + tt) * HD + d] = v;
            }
        }
    }
}

// Output projection: reads g_A, writes [B*T][D] to Y.
__global__ __launch_bounds__(256)
void out_gemm_kernel(const float* __restrict__ Wo, const float* __restrict__ bo,
                     float* __restrict__ Y)
{
    __shared__ __align__(16) char smem[SMEM_TOTAL];

    const int m0 = blockIdx.y * 128, n0 = blockIdx.x * 128;
    float acc[4][4][4];
    #pragma unroll
    for (int i = 0; i < 4; i++)
        #pragma unroll
        for (int j = 0; j < 4; j++)
            #pragma unroll
            for (int r = 0; r < 4; r++) acc[i][j][r] = 0.f;

    mma_core(g_A, Wo, m0, n0, smem, acc);

    const int lane = threadIdx.x & 31, warp = threadIdx.x >> 5;
    const int wm0 = (warp >> 2) * 64, wn0 = (warp & 3) * 32;
    const int g = lane >> 2, t = lane & 3;

    #pragma unroll
    for (int n8 = 0; n8 < 4; n8++) {
        const int n = n0 + wn0 + n8 * 8 + 2 * t;
        const float bx = bo[n], by = bo[n + 1];
        #pragma unroll
        for (int mi = 0; mi < 4; mi++) {
            #pragma unroll
            for (int half = 0; half < 2; half++) {
                const int m = m0 + wm0 + mi * 16 + g + half * 8;
                float2 v;
                v.x = acc[mi][n8][2 * half + 0] + bx;
                v.y = acc[mi][n8][2 * half + 1] + by;
                *(float2*)&Y[(size_t)m * D_MODEL + n] = v;
            }
        }
    }
}

// ---------------------------------------------------------------------------
// Attention. grid (T/64=32, B*H=32), 64 threads. Thread t owns query row
// qi = qt*64 + t. Decay bias -(i-j) kills everything beyond delta ~100, so we
// only process key tiles jt in [qt-2, qt] (skipped tiles: delta >= 129 =>
// weight underflows to exactly 0.0f, identical to the reference softmax).
// ---------------------------------------------------------------------------
__global__ __launch_bounds__(64)
void attn_kernel()
{
    __shared__ __align__(16) float Qt[64][64];  // Qt[d][t]
    __shared__ __align__(16) float Kt[64][64];  // Kt[d][j]
    __shared__ __align__(16) float Vs[64][64];  // Vs[j][d]

    int qt = blockIdx.x;
    int bh = blockIdx.y;
    int t  = threadIdx.x;

    const float* Qb = g_Q + (size_t)bh * TSEQ * HD;
    const float* Kb = g_K + (size_t)bh * TSEQ * HD;
    const float* Vb = g_V + (size_t)bh * TSEQ * HD;

    #pragma unroll
    for (int it = 0; it < 16; it++) {
        int f = (it << 6) + t;
        int r = f >> 4, c = (f & 15) << 2;
        float4 v = *(const float4*)&Qb[((size_t)qt * 64 + r) * HD + c];
        Qt[c + 0][r] = v.x; Qt[c + 1][r] = v.y;
        Qt[c + 2][r] = v.z; Qt[c + 3][r] = v.w;
    }

    float o[64];
    #pragma unroll
    for (int d = 0; d < 64; d++) o[d] = 0.f;
    float mrun = -1e30f, l = 0.f;
    int qi = qt * 64 + t;

    int jt0 = (qt >= 2) ? (qt - 2) : 0;
    for (int jt = jt0; jt <= qt; jt++) {
        __syncthreads();
        #pragma unroll
        for (int it = 0; it < 16; it++) {
            int f = (it << 6) + t;
            int r = f >> 4, c = (f & 15) << 2;
            float4 kv = *(const float4*)&Kb[((size_t)jt * 64 + r) * HD + c];
            Kt[c + 0][r] = kv.x; Kt[c + 1][r] = kv.y;
            Kt[c + 2][r] = kv.z; Kt[c + 3][r] = kv.w;
            float4 vv = *(const float4*)&Vb[((size_t)jt * 64 + r) * HD + c];
            *(float4*)&Vs[r][c] = vv;
        }
        __syncthreads();

        float s[64];
        #pragma unroll
        for (int j = 0; j < 64; j++) s[j] = 0.f;
        #pragma unroll 4
        for (int d = 0; d < 64; d++) {
            float qd = Qt[d][t];
            #pragma unroll
            for (int j4 = 0; j4 < 16; j4++) {
                float4 k4 = *(const float4*)&Kt[d][j4 << 2];
                s[4 * j4 + 0] += qd * k4.x;
                s[4 * j4 + 1] += qd * k4.y;
                s[4 * j4 + 2] += qd * k4.z;
                s[4 * j4 + 3] += qd * k4.w;
            }
        }

        float tmax = -1e30f;
        int base = jt * 64;
        #pragma unroll
        for (int j = 0; j < 64; j++) {
            int kj = base + j;
            float sc = (kj <= qi) ? (s[j] * 0.125f - (float)(qi - kj)) : -1e30f;
            s[j] = sc;
            tmax = fmaxf(tmax, sc);
        }
        float mnew = fmaxf(mrun, tmax);
        float corr = __expf(mrun - mnew);
        l *= corr;
        #pragma unroll
        for (int d = 0; d < 64; d++) o[d] *= corr;

        #pragma unroll
        for (int j = 0; j < 64; j++) {
            float p = __expf(s[j] - mnew);
            s[j] = p;
            l += p;
        }
        mrun = mnew;

        #pragma unroll
        for (int j = 0; j < 64; j++) {
            float pj = s[j];
            #pragma unroll
            for (int d4 = 0; d4 < 16; d4++) {
                float4 v4 = *(const float4*)&Vs[j][d4 << 2];
                o[4 * d4 + 0] += pj * v4.x;
                o[4 * d4 + 1] += pj * v4.y;
                o[4 * d4 + 2] += pj * v4.z;
                o[4 * d4 + 3] += pj * v4.w;
            }
        }
    }

    float inv = 1.0f / l;
    int b = bh >> 4, h = bh & 15;
    float* dst = g_A + ((size_t)b * TSEQ + qi) * D_MODEL + h * HD;
    #pragma unroll
    for (int d4 = 0; d4 < 16; d4++) {
        float4 v;
        v.x = o[4 * d4 + 0] * inv;
        v.y = o[4 * d4 + 1] * inv;
        v.z = o[4 * d4 + 2] * inv;
        v.w = o[4 * d4 + 3] * inv;
        *(float4*)&dst[d4 << 2] = v;
    }
}

// ---------------------------------------------------------------------------
extern "C" void kernel_launch(void* const* d_in, const int* in_sizes, int n_in,
                              void* d_out, int out_size)
{
    const float* x  = (const float*)d_in[0];
    const float* Wq = (const float*)d_in[1];
    const float* bq = (const float*)d_in[2];
    const float* Wk = (const float*)d_in[3];
    const float* bk = (const float*)d_in[4];
    const float* Wv = (const float*)d_in[5];
    const float* bv = (const float*)d_in[6];
    const float* Wo = (const float*)d_in[7];
    const float* bo = (const float*)d_in[8];
    float* out = (float*)d_out;

    dim3 ggrid(D_MODEL / 128, M_TOT / 128, 3);
    qkv_gemm_kernel<<<ggrid, 256>>>(x, Wq, bq, Wk, bk, Wv, bv);

    dim3 agrid(TSEQ / 64, BATCH * NHEADS);
    attn_kernel<<<agrid, 64>>>();

    dim3 ogrid(D_MODEL / 128, M_TOT / 128);
    out_gemm_kernel<<<ogrid, 256>>>(Wo, bo, out);
}

// round 8
// speedup vs baseline: 2.8934x; 1.2856x over previous
#include <cuda_runtime.h>
#include <cuda_bf16.h>
#include <cstdint>

#define D_MODEL 1024
#define NHEADS  16
#define HD      64
#define BATCH   2
#define TSEQ    2048
#define M_TOT   (BATCH * TSEQ)   // 4096

// Scratch (allocation-free rule: __device__ globals).
__device__ float g_Q[BATCH * NHEADS * TSEQ * HD];
__device__ float g_K[BATCH * NHEADS * TSEQ * HD];
__device__ float g_V[BATCH * NHEADS * TSEQ * HD];
__device__ float g_A[BATCH * TSEQ * D_MODEL];

static __device__ __forceinline__ uint32_t smem_u32(const void* p) {
    uint32_t a;
    asm("{ .reg .u64 t; cvta.to.shared.u64 t, %1; cvt.u32.u64 %0, t; }"
        : "=r"(a) : "l"(p));
    return a;
}

__device__ __forceinline__ void ldsm_x4(unsigned& r0, unsigned& r1,
                                        unsigned& r2, unsigned& r3,
                                        unsigned addr)
{
    asm volatile("ldmatrix.sync.aligned.m8n8.x4.shared.b16 {%0,%1,%2,%3}, [%4];"
                 : "=r"(r0), "=r"(r1), "=r"(r2), "=r"(r3) : "r"(addr));
}

__device__ __forceinline__ void ldsm_x4_t(unsigned& r0, unsigned& r1,
                                          unsigned& r2, unsigned& r3,
                                          unsigned addr)
{
    asm volatile("ldmatrix.sync.aligned.m8n8.x4.trans.shared.b16 {%0,%1,%2,%3}, [%4];"
                 : "=r"(r0), "=r"(r1), "=r"(r2), "=r"(r3) : "r"(addr));
}

__device__ __forceinline__ void mma_bf16(float* d, const unsigned* a,
                                         unsigned b0, unsigned b1)
{
    asm volatile(
        "mma.sync.aligned.m16n8k16.row.col.f32.bf16.bf16.f32 "
        "{%0,%1,%2,%3}, {%4,%5,%6,%7}, {%8,%9}, {%0,%1,%2,%3};"
        : "+f"(d[0]), "+f"(d[1]), "+f"(d[2]), "+f"(d[3])
        : "r"(a[0]), "r"(a[1]), "r"(a[2]), "r"(a[3]), "r"(b0), "r"(b1));
}

// ===========================================================================
// Projection GEMMs (proven R4 path): bf16-split mma.sync, 128x128x16 tiles.
// smem row: 80B = 32B hi | 32B lo | 16B pad.
// ===========================================================================
#define ROW_BYTES 80
#define STAGE_BYTES (128 * ROW_BYTES)
#define SMEM_TOTAL  (4 * STAGE_BYTES)

__device__ __forceinline__ void cvt8_store(unsigned addr_hi, float4 a, float4 b)
{
    float f[8] = {a.x, a.y, a.z, a.w, b.x, b.y, b.z, b.w};
    unsigned hi[4], lo[4];
    #pragma unroll
    for (int i = 0; i < 4; i++) {
        float x = f[2 * i], y = f[2 * i + 1];
        __nv_bfloat16 hx = __float2bfloat16_rn(x);
        __nv_bfloat16 hy = __float2bfloat16_rn(y);
        float lx = x - __bfloat162float(hx);
        float ly = y - __bfloat162float(hy);
        __nv_bfloat162 hp; hp.x = hx; hp.y = hy;
        __nv_bfloat162 lp = __floats2bfloat162_rn(lx, ly);
        hi[i] = *(unsigned*)&hp;
        lo[i] = *(unsigned*)&lp;
    }
    asm volatile("st.shared.v4.b32 [%0], {%1,%2,%3,%4};"
                 :: "r"(addr_hi), "r"(hi[0]), "r"(hi[1]), "r"(hi[2]), "r"(hi[3]));
    asm volatile("st.shared.v4.b32 [%0], {%1,%2,%3,%4};"
                 :: "r"(addr_hi + 32), "r"(lo[0]), "r"(lo[1]), "r"(lo[2]), "r"(lo[3]));
}

__device__ __forceinline__ void mma_core(
    const float* __restrict__ X, const float* __restrict__ W,
    int m0, int n0, char* smem, float acc[4][4][4])
{
    const int tid  = threadIdx.x;
    const int lane = tid & 31;
    const int warp = tid >> 5;
    const int wm0  = (warp >> 2) * 64;
    const int wn0  = (warp & 3) * 32;

    const int lrow  = tid >> 1;
    const int lhalf = tid & 1;

    const float* xp = X + (size_t)(m0 + lrow) * D_MODEL + lhalf * 8;
    const float* wp = W + (size_t)(n0 + lrow) * D_MODEL + lhalf * 8;

    const unsigned sAb = smem_u32(smem);
    const unsigned sBb = sAb + 2 * STAGE_BYTES;

    const unsigned stA = sAb + lrow * ROW_BYTES + lhalf * 16;
    const unsigned stB = sBb + lrow * ROW_BYTES + lhalf * 16;

    const int arow  = lane & 15;
    const int acoff = (lane >> 4) << 4;
    const unsigned ldA = sAb + (unsigned)(wm0 + arow) * ROW_BYTES + acoff;
    const int brow  = (lane & 7) + ((lane >> 4) << 3);
    const int bcoff = ((lane >> 3) & 1) << 4;
    const unsigned ldB = sBb + (unsigned)(wn0 + brow) * ROW_BYTES + bcoff;

    {
        float4 x0 = *(const float4*)xp;
        float4 x1 = *(const float4*)(xp + 4);
        float4 w0 = *(const float4*)wp;
        float4 w1 = *(const float4*)(wp + 4);
        cvt8_store(stA, x0, x1);
        cvt8_store(stB, w0, w1);
    }
    __syncthreads();

    unsigned buf = 0;
    for (int k0 = 16; k0 <= D_MODEL; k0 += 16) {
        const bool more = (k0 < D_MODEL);
        float4 nx0, nx1, nw0, nw1;
        if (more) {
            nx0 = *(const float4*)(xp + k0);
            nx1 = *(const float4*)(xp + k0 + 4);
            nw0 = *(const float4*)(wp + k0);
            nw1 = *(const float4*)(wp + k0 + 4);
        }

        const unsigned off = buf * STAGE_BYTES;
        unsigned bh[8], bl[8];
        ldsm_x4(bh[0], bh[1], bh[2], bh[3], ldB + off);
        ldsm_x4(bh[4], bh[5], bh[6], bh[7], ldB + off + 16 * ROW_BYTES);
        ldsm_x4(bl[0], bl[1], bl[2], bl[3], ldB + off + 32);
        ldsm_x4(bl[4], bl[5], bl[6], bl[7], ldB + off + 16 * ROW_BYTES + 32);

        #pragma unroll
        for (int mi = 0; mi < 4; mi++) {
            unsigned ah[4], al[4];
            const unsigned am = ldA + off + (unsigned)(mi * 16) * ROW_BYTES;
            ldsm_x4(ah[0], ah[1], ah[2], ah[3], am);
            ldsm_x4(al[0], al[1], al[2], al[3], am + 32);
            #pragma unroll
            for (int n8 = 0; n8 < 4; n8++) {
                mma_bf16(acc[mi][n8], ah, bh[2 * n8], bh[2 * n8 + 1]);
                mma_bf16(acc[mi][n8], ah, bl[2 * n8], bl[2 * n8 + 1]);
                mma_bf16(acc[mi][n8], al, bh[2 * n8], bh[2 * n8 + 1]);
            }
        }

        if (more) {
            const unsigned o2 = (buf ^ 1u) * STAGE_BYTES;
            cvt8_store(stA + o2, nx0, nx1);
            cvt8_store(stB + o2, nw0, nw1);
            __syncthreads();
            buf ^= 1u;
        }
    }
}

__global__ __launch_bounds__(256)
void qkv_gemm_kernel(const float* __restrict__ X,
                     const float* __restrict__ Wq, const float* __restrict__ bq,
                     const float* __restrict__ Wk, const float* __restrict__ bk,
                     const float* __restrict__ Wv, const float* __restrict__ bv)
{
    __shared__ __align__(16) char smem[SMEM_TOTAL];

    const float* W; const float* bias; float* dst;
    if (blockIdx.z == 0)      { W = Wq; bias = bq; dst = g_Q; }
    else if (blockIdx.z == 1) { W = Wk; bias = bk; dst = g_K; }
    else                      { W = Wv; bias = bv; dst = g_V; }

    const int m0 = blockIdx.y * 128, n0 = blockIdx.x * 128;
    float acc[4][4][4];
    #pragma unroll
    for (int i = 0; i < 4; i++)
        #pragma unroll
        for (int j = 0; j < 4; j++)
            #pragma unroll
            for (int r = 0; r < 4; r++) acc[i][j][r] = 0.f;

    mma_core(X, W, m0, n0, smem, acc);

    const int lane = threadIdx.x & 31, warp = threadIdx.x >> 5;
    const int wm0 = (warp >> 2) * 64, wn0 = (warp & 3) * 32;
    const int g = lane >> 2, t = lane & 3;

    #pragma unroll
    for (int n8 = 0; n8 < 4; n8++) {
        const int n = n0 + wn0 + n8 * 8 + 2 * t;
        const float bx = bias[n], by = bias[n + 1];
        const int h = n >> 6, d = n & 63;
        #pragma unroll
        for (int mi = 0; mi < 4; mi++) {
            #pragma unroll
            for (int half = 0; half < 2; half++) {
                const int m = m0 + wm0 + mi * 16 + g + half * 8;
                const int b = m >> 11, tt = m & (TSEQ - 1);
                float2 v;
                v.x = acc[mi][n8][2 * half + 0] + bx;
                v.y = acc[mi][n8][2 * half + 1] + by;
                *(float2*)&dst[(((size_t)b * NHEADS + h) * TSEQ + tt) * HD + d] = v;
            }
        }
    }
}

__global__ __launch_bounds__(256)
void out_gemm_kernel(const float* __restrict__ Wo, const float* __restrict__ bo,
                     float* __restrict__ Y)
{
    __shared__ __align__(16) char smem[SMEM_TOTAL];

    const int m0 = blockIdx.y * 128, n0 = blockIdx.x * 128;
    float acc[4][4][4];
    #pragma unroll
    for (int i = 0; i < 4; i++)
        #pragma unroll
        for (int j = 0; j < 4; j++)
            #pragma unroll
            for (int r = 0; r < 4; r++) acc[i][j][r] = 0.f;

    mma_core(g_A, Wo, m0, n0, smem, acc);

    const int lane = threadIdx.x & 31, warp = threadIdx.x >> 5;
    const int wm0 = (warp >> 2) * 64, wn0 = (warp & 3) * 32;
    const int g = lane >> 2, t = lane & 3;

    #pragma unroll
    for (int n8 = 0; n8 < 4; n8++) {
        const int n = n0 + wn0 + n8 * 8 + 2 * t;
        const float bx = bo[n], by = bo[n + 1];
        #pragma unroll
        for (int mi = 0; mi < 4; mi++) {
            #pragma unroll
            for (int half = 0; half < 2; half++) {
                const int m = m0 + wm0 + mi * 16 + g + half * 8;
                float2 v;
                v.x = acc[mi][n8][2 * half + 0] + bx;
                v.y = acc[mi][n8][2 * half + 1] + by;
                *(float2*)&Y[(size_t)m * D_MODEL + n] = v;
            }
        }
    }
}

// ===========================================================================
// MMA flash-attention. grid (T/64=32, B*H=32), 128 threads = 4 warps.
// Warp w owns queries [qt*64 + w*16, +16). Key tiles jt in [qt-2, qt]
// (decay -(i-j): delta >= 129 underflows to 0, matches reference exactly).
// QK^T and P*V on tensor cores, bf16 hi/lo 3-term split.
// smem tiles: 64x64 bf16, 128B rows, SW128 xor-swizzle.
// ===========================================================================

// Convert+store 32 consecutive values of one row into hi/lo swizzled tiles
// (128B rows: base = row*128 + half*64 bytes).
static __device__ __forceinline__ void cvt_store32(
    uint32_t hi_buf, uint32_t lo_buf, int row, int half, const float* gp)
{
    uint32_t base_off = (uint32_t)row * 128u + (uint32_t)half * 64u;
    #pragma unroll
    for (int i = 0; i < 4; i++) {
        float4 va = *(const float4*)(gp + i * 8);
        float4 vb = *(const float4*)(gp + i * 8 + 4);
        float f[8] = {va.x, va.y, va.z, va.w, vb.x, vb.y, vb.z, vb.w};
        unsigned hi[4], lo[4];
        #pragma unroll
        for (int q = 0; q < 4; q++) {
            float x = f[2 * q], y = f[2 * q + 1];
            __nv_bfloat162 hp = __floats2bfloat162_rn(x, y);
            float lx = x - __low2float(hp), ly = y - __high2float(hp);
            __nv_bfloat162 lp = __floats2bfloat162_rn(lx, ly);
            hi[q] = *(unsigned*)&hp;
            lo[q] = *(unsigned*)&lp;
        }
        uint32_t off = base_off + (uint32_t)i * 16u;
        uint32_t sw = off ^ ((off >> 3) & 0x70u);
        asm volatile("st.shared.v4.b32 [%0], {%1,%2,%3,%4};"
                     :: "r"(hi_buf + sw), "r"(hi[0]), "r"(hi[1]), "r"(hi[2]), "r"(hi[3]));
        asm volatile("st.shared.v4.b32 [%0], {%1,%2,%3,%4};"
                     :: "r"(lo_buf + sw), "r"(lo[0]), "r"(lo[1]), "r"(lo[2]), "r"(lo[3]));
    }
}

// pack two fp32 -> bf16x2 hi and residual lo
static __device__ __forceinline__ void packpair(float x, float y,
                                                unsigned& h, unsigned& l)
{
    __nv_bfloat162 hp = __floats2bfloat162_rn(x, y);
    float lx = x - __low2float(hp), ly = y - __high2float(hp);
    __nv_bfloat162 lp = __floats2bfloat162_rn(lx, ly);
    h = *(unsigned*)&hp;
    l = *(unsigned*)&lp;
}

__global__ __launch_bounds__(128)
void attn_mma_kernel()
{
    __shared__ __align__(16) char sQh[8192], sQl[8192];
    __shared__ __align__(16) char sKh[8192], sKl[8192];
    __shared__ __align__(16) char sVh[8192], sVl[8192];

    const int tid  = threadIdx.x;
    const int lane = tid & 31;
    const int warp = tid >> 5;
    const int qt   = blockIdx.x;
    const int bh   = blockIdx.y;

    const uint32_t uQh = smem_u32(sQh), uQl = smem_u32(sQl);
    const uint32_t uKh = smem_u32(sKh), uKl = smem_u32(sKl);
    const uint32_t uVh = smem_u32(sVh), uVl = smem_u32(sVl);

    const float* Qg = g_Q + (size_t)bh * TSEQ * HD;
    const float* Kg = g_K + (size_t)bh * TSEQ * HD;
    const float* Vg = g_V + (size_t)bh * TSEQ * HD;

    const int lrow  = tid >> 1;   // 0..63
    const int lhalf = tid & 1;

    // ---- stage Q tile, load Q fragments (held in regs for all ktiles) ----
    cvt_store32(uQh, uQl, lrow, lhalf,
                Qg + ((size_t)qt * 64 + lrow) * HD + lhalf * 32);
    __syncthreads();

    unsigned qh[4][4], ql[4][4];
    {
        const int qrow = warp * 16 + (lane & 15);
        const int sel  = qrow & 7;
        #pragma unroll
        for (int ks = 0; ks < 4; ks++) {
            const int c16 = ks * 2 + (lane >> 4);
            const unsigned a = (unsigned)qrow * 128u + (unsigned)((c16 ^ sel) << 4);
            ldsm_x4(qh[ks][0], qh[ks][1], qh[ks][2], qh[ks][3], uQh + a);
            ldsm_x4(ql[ks][0], ql[ks][1], ql[ks][2], ql[ks][3], uQl + a);
        }
    }

    // ldmatrix lane geometry for K (no trans) and V (trans)
    const int krow_b = (lane & 7) + ((lane >> 4) << 3);
    const int kc16_b = (lane >> 3) & 1;
    const int vrow_b = (lane & 7) + (((lane >> 3) & 1) << 3);
    const int vc16_b = lane >> 4;

    float o[8][4];
    #pragma unroll
    for (int i = 0; i < 8; i++)
        #pragma unroll
        for (int r = 0; r < 4; r++) o[i][r] = 0.f;
    float m0r = -1e30f, m1r = -1e30f, l0 = 0.f, l1 = 0.f;

    const int jt0 = (qt >= 2) ? (qt - 2) : 0;
    for (int jt = jt0; jt <= qt; jt++) {
        __syncthreads();
        cvt_store32(uKh, uKl, lrow, lhalf,
                    Kg + ((size_t)jt * 64 + lrow) * HD + lhalf * 32);
        cvt_store32(uVh, uVl, lrow, lhalf,
                    Vg + ((size_t)jt * 64 + lrow) * HD + lhalf * 32);
        __syncthreads();

        // ---- S = Q K^T ----
        float s[8][4];
        #pragma unroll
        for (int i = 0; i < 8; i++)
            #pragma unroll
            for (int r = 0; r < 4; r++) s[i][r] = 0.f;

        #pragma unroll
        for (int ng = 0; ng < 4; ng++) {
            #pragma unroll
            for (int ks = 0; ks < 4; ks++) {
                const int jr = ng * 16 + krow_b;
                const int c16 = ks * 2 + kc16_b;
                const unsigned a = (unsigned)jr * 128u
                                 + (unsigned)((c16 ^ (jr & 7)) << 4);
                unsigned kh[4], kl[4];
                ldsm_x4(kh[0], kh[1], kh[2], kh[3], uKh + a);
                ldsm_x4(kl[0], kl[1], kl[2], kl[3], uKl + a);
                mma_bf16(s[ng * 2],     qh[ks], kh[0], kh[1]);
                mma_bf16(s[ng * 2],     qh[ks], kl[0], kl[1]);
                mma_bf16(s[ng * 2],     ql[ks], kh[0], kh[1]);
                mma_bf16(s[ng * 2 + 1], qh[ks], kh[2], kh[3]);
                mma_bf16(s[ng * 2 + 1], qh[ks], kl[2], kl[3]);
                mma_bf16(s[ng * 2 + 1], ql[ks], kh[2], kh[3]);
            }
        }

        // ---- softmax (online) ----
        // thread rows: r = warp*16 + lane/4 and r+8; cols: n8*8 + (lane&3)*2 +{0,1}
        const int dbase = (qt - jt) * 64 + warp * 16 + (lane >> 2);
        float rmax0 = -1e30f, rmax1 = -1e30f;
        #pragma unroll
        for (int n8 = 0; n8 < 8; n8++) {
            const int d0 = dbase - (n8 * 8 + (lane & 3) * 2);
            s[n8][0] = (d0     >= 0) ? s[n8][0] * 0.125f - (float)d0       : -1e30f;
            s[n8][1] = (d0 - 1 >= 0) ? s[n8][1] * 0.125f - (float)(d0 - 1) : -1e30f;
            s[n8][2] = (d0 + 8 >= 0) ? s[n8][2] * 0.125f - (float)(d0 + 8) : -1e30f;
            s[n8][3] = (d0 + 7 >= 0) ? s[n8][3] * 0.125f - (float)(d0 + 7) : -1e30f;
            rmax0 = fmaxf(rmax0, fmaxf(s[n8][0], s[n8][1]));
            rmax1 = fmaxf(rmax1, fmaxf(s[n8][2], s[n8][3]));
        }
        rmax0 = fmaxf(rmax0, __shfl_xor_sync(0xffffffffu, rmax0, 1));
        rmax0 = fmaxf(rmax0, __shfl_xor_sync(0xffffffffu, rmax0, 2));
        rmax1 = fmaxf(rmax1, __shfl_xor_sync(0xffffffffu, rmax1, 1));
        rmax1 = fmaxf(rmax1, __shfl_xor_sync(0xffffffffu, rmax1, 2));

        const float mn0 = fmaxf(m0r, rmax0), mn1 = fmaxf(m1r, rmax1);
        const float c0 = __expf(m0r - mn0),  c1 = __expf(m1r - mn1);
        m0r = mn0; m1r = mn1;
        l0 *= c0;  l1 *= c1;
        #pragma unroll
        for (int n8 = 0; n8 < 8; n8++) {
            o[n8][0] *= c0; o[n8][1] *= c0;
            o[n8][2] *= c1; o[n8][3] *= c1;
        }
        float ps0 = 0.f, ps1 = 0.f;
        #pragma unroll
        for (int n8 = 0; n8 < 8; n8++) {
            s[n8][0] = __expf(s[n8][0] - mn0);
            s[n8][1] = __expf(s[n8][1] - mn0);
            s[n8][2] = __expf(s[n8][2] - mn1);
            s[n8][3] = __expf(s[n8][3] - mn1);
            ps0 += s[n8][0] + s[n8][1];
            ps1 += s[n8][2] + s[n8][3];
        }
        l0 += ps0; l1 += ps1;

        // ---- pack P into A fragments (C->A layout identity) ----
        unsigned ph[4][4], pl[4][4];
        #pragma unroll
        for (int kc = 0; kc < 4; kc++) {
            packpair(s[2 * kc][0],     s[2 * kc][1],     ph[kc][0], pl[kc][0]);
            packpair(s[2 * kc][2],     s[2 * kc][3],     ph[kc][1], pl[kc][1]);
            packpair(s[2 * kc + 1][0], s[2 * kc + 1][1], ph[kc][2], pl[kc][2]);
            packpair(s[2 * kc + 1][2], s[2 * kc + 1][3], ph[kc][3], pl[kc][3]);
        }

        // ---- O += P V ----
        #pragma unroll
        for (int ng = 0; ng < 4; ng++) {
            #pragma unroll
            for (int kc = 0; kc < 4; kc++) {
                const int jr = kc * 16 + vrow_b;
                const int c16 = ng * 2 + vc16_b;
                const unsigned a = (unsigned)jr * 128u
                                 + (unsigned)((c16 ^ (jr & 7)) << 4);
                unsigned vh[4], vl[4];
                ldsm_x4_t(vh[0], vh[1], vh[2], vh[3], uVh + a);
                ldsm_x4_t(vl[0], vl[1], vl[2], vl[3], uVl + a);
                mma_bf16(o[ng * 2],     ph[kc], vh[0], vh[1]);
                mma_bf16(o[ng * 2],     ph[kc], vl[0], vl[1]);
                mma_bf16(o[ng * 2],     pl[kc], vh[0], vh[1]);
                mma_bf16(o[ng * 2 + 1], ph[kc], vh[2], vh[3]);
                mma_bf16(o[ng * 2 + 1], ph[kc], vl[2], vl[3]);
                mma_bf16(o[ng * 2 + 1], pl[kc], vh[2], vh[3]);
            }
        }
    }

    // ---- epilogue ----
    l0 += __shfl_xor_sync(0xffffffffu, l0, 1);
    l0 += __shfl_xor_sync(0xffffffffu, l0, 2);
    l1 += __shfl_xor_sync(0xffffffffu, l1, 1);
    l1 += __shfl_xor_sync(0xffffffffu, l1, 2);
    const float i0 = 1.f / l0, i1 = 1.f / l1;

    const int row0 = qt * 64 + warp * 16 + (lane >> 2);
    const int b = bh >> 4, h = bh & 15;
    float* base0 = g_A + ((size_t)b * TSEQ + row0) * D_MODEL + h * HD;
    float* base1 = base0 + 8 * D_MODEL;
    #pragma unroll
    for (int n8 = 0; n8 < 8; n8++) {
        const int col = n8 * 8 + (lane & 3) * 2;
        float2 v0, v1;
        v0.x = o[n8][0] * i0; v0.y = o[n8][1] * i0;
        v1.x = o[n8][2] * i1; v1.y = o[n8][3] * i1;
        *(float2*)(base0 + col) = v0;
        *(float2*)(base1 + col) = v1;
    }
}

// ---------------------------------------------------------------------------
extern "C" void kernel_launch(void* const* d_in, const int* in_sizes, int n_in,
                              void* d_out, int out_size)
{
    const float* x  = (const float*)d_in[0];
    const float* Wq = (const float*)d_in[1];
    const float* bq = (const float*)d_in[2];
    const float* Wk = (const float*)d_in[3];
    const float* bk = (const float*)d_in[4];
    const float* Wv = (const float*)d_in[5];
    const float* bv = (const float*)d_in[6];
    const float* Wo = (const float*)d_in[7];
    const float* bo = (const float*)d_in[8];
    float* out = (float*)d_out;

    dim3 ggrid(D_MODEL / 128, M_TOT / 128, 3);
    qkv_gemm_kernel<<<ggrid, 256>>>(x, Wq, bq, Wk, bk, Wv, bv);

    dim3 agrid(TSEQ / 64, BATCH * NHEADS);
    attn_mma_kernel<<<agrid, 128>>>();

    dim3 ogrid(D_MODEL / 128, M_TOT / 128);
    out_gemm_kernel<<<ogrid, 256>>>(Wo, bo, out);
}